// round 13
// baseline (speedup 1.0000x reference)
#include <cuda_runtime.h>
#include <math.h>

// ---------------- problem constants ----------------
#define MPTS 5151          // triangle mesh points (101*102/2)
#define NB   16            // batch
#define NT   1024          // decoder timesteps
#define NS   256           // encoder seq len
#define NH   256           // hidden
#define NG   21            // scan chunks per batch (21*16 = 336 CTAs ~ 2.3/SM)
#define TP   36            // mesh points per MLP CTA (144 CTAs = one balanced wave)
#define ACTW 260           // padded activation row stride (16B-aligned rows)

// output layout: b_out | density | m | initial_states | mesh
#define OFF_BOUT 0
#define OFF_DENS (NB*NT)                       // 16384
#define OFF_M    (OFF_DENS + NB*MPTS)          // 98800
#define OFF_INIT (OFF_M + NB*NT)               // 115184
#define OFF_MESH (OFF_INIT + NB*MPTS)          // 197600

// ---------------- device scratch (static, no allocs) ----------------
__device__ float g_density[MPTS];
__device__ float g_dpart[144];
__device__ float g_dsum;
__device__ float g_ctx[NB*NH];
__device__ float g_ctxp[NB*NH];
__device__ float g_wtab[NB*NT*256];            // per (b,t): [0..100]=w_up(alpha), [128..228]=w_dn(beta)
__device__ float g_mpart[NB*NG*NT];

__device__ __forceinline__ float sigmoid_acc(float x){
    return 1.0f / (1.0f + expf(-x));
}

// ---- f32x2 packed helpers (Blackwell FFMA2: only reachable via PTX) ----
__device__ __forceinline__ unsigned long long pk2(float x){
    unsigned long long r;
    unsigned u = __float_as_uint(x);
    asm("mov.b64 %0, {%1, %1};" : "=l"(r) : "r"(u));
    return r;
}
__device__ __forceinline__ void ffma2(unsigned long long &acc,
                                      unsigned long long a, unsigned long long b){
    asm("fma.rn.f32x2 %0, %1, %2, %0;" : "+l"(acc) : "l"(a), "l"(b));
}
__device__ __forceinline__ float2 up2(unsigned long long v){
    unsigned lo, hi;
    asm("mov.b64 {%0, %1}, %2;" : "=r"(lo), "=r"(hi) : "l"(v));
    float2 r; r.x = __uint_as_float(lo); r.y = __uint_as_float(hi);
    return r;
}

// ================= fused density MLP =================
// One CTA = 36 mesh points carried through input layer + 3 residual layers +
// output head, activations resident in shared memory. 192 threads:
// warp w owns points p0=6w..6w+5; lane owns 8 output columns j0=8*lane.
// Inner product uses f32x2 FMA: W pairs read directly as 64-bit from smem.
extern __shared__ float smdyn[];

__global__ void __launch_bounds__(192) k_mlp(const float* __restrict__ mesh,
    const float* __restrict__ Win, const float* __restrict__ bin,
    const float* __restrict__ Wr,  const float* __restrict__ br,
    const float* __restrict__ Wout, const float* __restrict__ bout)
{
    float* act = smdyn;                 // TP*ACTW floats
    float* ws  = smdyn + TP*ACTW;       // 32*NH floats (k-chunk of W)
    float* dsh = ws + 32*NH;            // TP floats (per-point density)
    int tid  = threadIdx.x;
    int lane = tid & 31, wid = tid >> 5;
    int p0 = wid * 6;
    int j0 = lane * 8;
    int pg = blockIdx.x * TP;

    // ---- input layer: act = relu(mesh @ Win + bin) ----
    {
        float be[6], al[6];
        #pragma unroll
        for (int i = 0; i < 6; i++){
            int p = pg + p0 + i;
            be[i] = 0.f; al[i] = 0.f;
            if (p < MPTS){ be[i] = mesh[2*p]; al[i] = mesh[2*p+1]; }
        }
        #pragma unroll
        for (int jj = 0; jj < 8; jj++){
            int j = j0 + jj;
            float w0 = Win[j], w1 = Win[NH+j], bb = bin[j];
            #pragma unroll
            for (int i = 0; i < 6; i++){
                float v = fmaf(be[i], w0, fmaf(al[i], w1, bb));
                act[(p0+i)*ACTW + j] = fmaxf(v, 0.f);
            }
        }
    }
    __syncthreads();

    // ---- 3 residual layers: act = act + relu(act @ W + b) ----
    for (int L = 0; L < 3; L++){
        const float* W    = Wr + L*NH*NH;
        const float* bias = br + L*NH;
        unsigned long long acc[6][4];
        #pragma unroll
        for (int i = 0; i < 6; i++)
            #pragma unroll
            for (int q = 0; q < 4; q++) acc[i][q] = 0ULL;

        for (int kc = 0; kc < NH; kc += 32){
            // stage 32xNH weight chunk (2048 float4, 192 threads)
            for (int idx = tid; idx < 2048; idx += 192){
                int row = idx >> 6, col = (idx & 63) * 4;
                *reinterpret_cast<float4*>(&ws[row*NH + col]) =
                    *reinterpret_cast<const float4*>(&W[(kc+row)*NH + col]);
            }
            __syncthreads();
            #pragma unroll 4
            for (int k = 0; k < 32; k++){
                unsigned long long ad[6];
                #pragma unroll
                for (int i = 0; i < 6; i++)
                    ad[i] = pk2(act[(p0+i)*ACTW + kc + k]);
                ulonglong2 w0 = *reinterpret_cast<const ulonglong2*>(&ws[k*NH + j0]);
                ulonglong2 w1 = *reinterpret_cast<const ulonglong2*>(&ws[k*NH + j0 + 4]);
                #pragma unroll
                for (int i = 0; i < 6; i++){
                    ffma2(acc[i][0], ad[i], w0.x);
                    ffma2(acc[i][1], ad[i], w0.y);
                    ffma2(acc[i][2], ad[i], w1.x);
                    ffma2(acc[i][3], ad[i], w1.y);
                }
            }
            __syncthreads();
        }
        // epilogue: own (p,j) cells only -> safe in-place after last sync
        float4 b0 = *reinterpret_cast<const float4*>(&bias[j0]);
        float4 b1 = *reinterpret_cast<const float4*>(&bias[j0+4]);
        #pragma unroll
        for (int i = 0; i < 6; i++){
            float* arow = &act[(p0+i)*ACTW + j0];
            float4 x0 = *reinterpret_cast<float4*>(arow);
            float4 x1 = *reinterpret_cast<float4*>(arow + 4);
            float2 f0 = up2(acc[i][0]), f1 = up2(acc[i][1]);
            float2 f2 = up2(acc[i][2]), f3 = up2(acc[i][3]);
            x0.x += fmaxf(f0.x + b0.x, 0.f);
            x0.y += fmaxf(f0.y + b0.y, 0.f);
            x0.z += fmaxf(f1.x + b0.z, 0.f);
            x0.w += fmaxf(f1.y + b0.w, 0.f);
            x1.x += fmaxf(f2.x + b1.x, 0.f);
            x1.y += fmaxf(f2.y + b1.y, 0.f);
            x1.z += fmaxf(f3.x + b1.z, 0.f);
            x1.w += fmaxf(f3.y + b1.w, 0.f);
            *reinterpret_cast<float4*>(arow)     = x0;
            *reinterpret_cast<float4*>(arow + 4) = x1;
        }
        __syncthreads();
    }

    // ---- output head: density = sigmoid(act @ Wout + bout) ----
    {
        float bo = bout[0];
        #pragma unroll
        for (int i = 0; i < 6; i++){
            int pl = p0 + i;
            float a = 0.f;
            #pragma unroll
            for (int q = 0; q < 8; q++){
                int h = lane + q*32;
                a = fmaf(act[pl*ACTW + h], Wout[h], a);
            }
            #pragma unroll
            for (int off = 16; off; off >>= 1)
                a += __shfl_xor_sync(0xffffffffu, a, off);
            if (lane == 0){
                int p = pg + pl;
                float dd = (p < MPTS) ? sigmoid_acc(a + bo) : 0.f;
                if (p < MPTS) g_density[p] = dd;
                dsh[pl] = dd;
            }
        }
    }
    __syncthreads();
    if (tid == 0){
        float s = 0.f;
        #pragma unroll
        for (int i = 0; i < TP; i++) s += dsh[i];
        g_dpart[blockIdx.x] = s;
    }
}

// ---------------- dsum over 144 CTA partials ----------------
__global__ void k_dsum(){
    __shared__ float sh[256];
    float a = (threadIdx.x < 144) ? g_dpart[threadIdx.x] : 0.f;
    sh[threadIdx.x] = a; __syncthreads();
    for (int s = 128; s; s >>= 1){
        if (threadIdx.x < (unsigned)s) sh[threadIdx.x] += sh[threadIdx.x+s];
        __syncthreads();
    }
    if (threadIdx.x == 0) g_dsum = sh[0];
}

// ---------------- encoder context ----------------
__global__ void k_ctx(const float* __restrict__ enc, const float* __restrict__ mask,
                      const float* __restrict__ Ws, const float* __restrict__ bs){
    __shared__ float e0[NS], e1[NS], mk[NS];
    int b = blockIdx.x, h = threadIdx.x;
    e0[h] = enc[(b*NS + h)*2];
    e1[h] = enc[(b*NS + h)*2 + 1];
    mk[h] = mask[b*NS + h];
    __syncthreads();
    float w0 = Ws[h], w1 = Ws[NH + h], bb = bs[h];
    float acc = 0.0f, ms = 0.0f;
    for (int s = 0; s < NS; s++){
        float v = fmaxf(fmaf(e0[s], w0, fmaf(e1[s], w1, bb)), 0.0f);
        acc = fmaf(v, mk[s], acc);
        ms += mk[s];
    }
    g_ctx[b*NH + h] = acc / fmaxf(ms, 1.0f);
}

__global__ void k_ctxp(const float* __restrict__ Wc){
    __shared__ float c[NH];
    int b = blockIdx.x, j = threadIdx.x;
    c[j] = g_ctx[b*NH + j];
    __syncthreads();
    float acc = 0.0f;
    #pragma unroll 4
    for (int h = 0; h < NH; h++) acc = fmaf(c[h], Wc[h*NH + j], acc);
    g_ctxp[b*NH + j] = acc;
}

// ---------------- initial states ----------------
__global__ void k_init(const float* __restrict__ mesh,
                       const float* __restrict__ Wm, const float* __restrict__ bm,
                       const float* __restrict__ Wo, const float* __restrict__ bo,
                       float* __restrict__ out){
    __shared__ float wm0[NH], wm1[NH], wm2[NH], wo[NH], pre[NH];
    int b = blockIdx.y;
    int tid = threadIdx.x;
    wm0[tid] = Wm[tid]; wm1[tid] = Wm[NH+tid]; wm2[tid] = Wm[2*NH+tid];
    wo[tid]  = Wo[tid];
    pre[tid] = g_ctxp[b*NH + tid] + bm[tid];
    __syncthreads();
    int p = blockIdx.x*256 + tid;
    if (p >= MPTS) return;
    float be = mesh[2*p], al = mesh[2*p+1], d = g_density[p];
    float acc = 0.0f;
    #pragma unroll 4
    for (int h = 0; h < NH; h++){
        float z = fmaf(be, wm0[h], fmaf(al, wm1[h], fmaf(d, wm2[h], pre[h])));
        z = fmaxf(z, 0.0f);
        acc = fmaf(z, wo[h], acc);
    }
    out[OFF_INIT + b*MPTS + p] = tanhf(acc + bo[0]);
}

// ---------------- sigmoid tables: per (b,t), 101 alpha + 101 beta values ----------------
__global__ void k_tab(const float* __restrict__ dec, const float* __restrict__ mesh){
    int q = blockIdx.x;              // q = b*NT + t
    int j = threadIdx.x;
    float h = dec[q];
    float v = 0.0f;
    if (j < 101){
        float gv = mesh[2*j + 1];    // grid values = alpha of first 101 points (beta=0 row)
        v = sigmoid_acc((h - gv) / 0.001f);
    } else if (j >= 128 && j < 229){
        float gv = mesh[2*(j-128) + 1];
        v = sigmoid_acc((gv - h) / 0.001f);
    }
    g_wtab[(size_t)q*256 + j] = v;
}

// ---------------- relay scan ----------------
// 1 point/thread, 256 pts/CTA, NG=21 chunks x 16 batches = 336 CTAs.
// Deferred reduction: threads write per-step partials to psum; after each
// 8-step block, warp w reduces step w (8 LDS + 5 shfl instead of 5 shfl/step).
// Next table block is prefetched during the reduce phase.
__global__ void __launch_bounds__(256) k_scan(const float* __restrict__ mesh,
                                              const float* __restrict__ outro){
    __shared__ float tabS[8][256];
    __shared__ float psum[8][256];
    int g = blockIdx.x, b = blockIdx.y;
    int tid = threadIdx.x, warp = tid >> 5, lane = tid & 31;
    int p = g*256 + tid;

    float s = 0.f, dn = 0.f; int ia = 0, ib = 128;
    if (p < MPTS){
        float be = mesh[2*p], al = mesh[2*p+1];
        ia = __float2int_rn(al * 100.0f);
        ib = __float2int_rn(be * 100.0f) + 128;
        dn = g_density[p];
        s  = outro[OFF_INIT + b*MPTS + p];
    }

    const float4* tg = reinterpret_cast<const float4*>(g_wtab + (size_t)b*NT*256);
    float4* ts4 = reinterpret_cast<float4*>(&tabS[0][0]);
    ts4[tid] = tg[tid]; ts4[tid + 256] = tg[tid + 256];   // preload bt=0

    for (int bt = 0; bt < NT/8; bt++){
        __syncthreads();                    // tab(bt) visible, psum(bt-1) consumed
        #pragma unroll
        for (int st = 0; st < 8; st++){
            float wu = tabS[st][ia];
            float wd = tabS[st][ib];
            s = fmaf(wu,  1.0f - s, s);     // s += wu*(1-s)
            s = fmaf(wd, -1.0f - s, s);     // s += wd*(-1-s)
            psum[st][tid] = dn * s;
        }
        __syncthreads();                    // psum ready, tabS free
        if (bt + 1 < NT/8){                 // prefetch next table block
            int o = (bt + 1) * 512;
            ts4[tid] = tg[o + tid]; ts4[tid + 256] = tg[o + tid + 256];
        }
        float a = 0.f;                      // warp w reduces step w
        #pragma unroll
        for (int q = 0; q < 8; q++) a += psum[warp][lane + q*32];
        #pragma unroll
        for (int off = 16; off; off >>= 1)
            a += __shfl_xor_sync(0xffffffffu, a, off);
        if (lane == 0) g_mpart[((b*NG) + g)*NT + bt*8 + warp] = a;
    }
}

// ---------------- final: m, b_out ----------------
__global__ void k_final(const float* __restrict__ dec,
                        const float* __restrict__ hsr, const float* __restrict__ msr,
                        const float* __restrict__ mor, float* __restrict__ out){
    int idx = blockIdx.x*256 + threadIdx.x;
    if (idx >= NB*NT) return;
    int b = idx >> 10, t = idx & 1023;
    float a = 0.0f;
    #pragma unroll
    for (int g = 0; g < NG; g++) a += g_mpart[((b*NG)+g)*NT + t];
    float m = a / g_dsum;
    float hs = 10.0f * sigmoid_acc(hsr[0]);
    float ms = 10.0f * sigmoid_acc(msr[0]);
    float mo = fmaf(20.0f, sigmoid_acc(mor[0]), -10.0f);
    float h = dec[idx];
    out[OFF_M + idx] = m;
    out[OFF_BOUT + idx] = fmaf(hs, h, fmaf(ms, m, mo));
}

// ---------------- broadcasts: density, mesh ----------------
__global__ void k_bcast(const float* __restrict__ mesh, float* __restrict__ out){
    int idx = blockIdx.x*256 + threadIdx.x;
    const int nd = NB*MPTS;
    if (idx < nd){
        out[OFF_DENS + idx] = g_density[idx % MPTS];
    } else {
        int i2 = idx - nd;
        if (i2 < NB*MPTS*2)
            out[OFF_MESH + i2] = mesh[i2 % (MPTS*2)];
    }
}

// ---------------- launch ----------------
extern "C" void kernel_launch(void* const* d_in, const int* in_sizes, int n_in,
                              void* d_out, int out_size){
    const float* enc   = (const float*)d_in[0];
    const float* dec   = (const float*)d_in[1];
    const float* emask = (const float*)d_in[2];
    const float* mesh  = (const float*)d_in[3];
    const float* Win   = (const float*)d_in[4];
    const float* bin   = (const float*)d_in[5];
    const float* Wr    = (const float*)d_in[6];
    const float* br    = (const float*)d_in[7];
    const float* Wout  = (const float*)d_in[8];
    const float* bout  = (const float*)d_in[9];
    const float* Ws    = (const float*)d_in[10];
    const float* bs    = (const float*)d_in[11];
    const float* Wm    = (const float*)d_in[12];
    const float* Wc    = (const float*)d_in[13];
    const float* bm    = (const float*)d_in[14];
    const float* Wo    = (const float*)d_in[15];
    const float* bo    = (const float*)d_in[16];
    const float* hsr   = (const float*)d_in[17];
    const float* msr   = (const float*)d_in[18];
    const float* mor   = (const float*)d_in[19];
    float* out = (float*)d_out;

    // fused density MLP (batch-independent): 144 CTAs, one wave
    const int smbytes = (TP*ACTW + 32*NH + 64) * (int)sizeof(float);  // ~70.5KB
    static int attr_done = 0;
    if (!attr_done){
        cudaFuncSetAttribute(k_mlp, cudaFuncAttributeMaxDynamicSharedMemorySize, smbytes);
        attr_done = 1;
    }
    k_mlp<<<(MPTS + TP - 1)/TP, 192, smbytes>>>(mesh, Win, bin, Wr, br, Wout, bout);
    k_dsum<<<1, 256>>>();

    // encoder path
    k_ctx<<<NB, 256>>>(enc, emask, Ws, bs);
    k_ctxp<<<NB, 256>>>(Wc);

    // initial states (writes d_out init region)
    {
        dim3 g((MPTS + 255)/256, NB);
        k_init<<<g, 256>>>(mesh, Wm, bm, Wo, bo, out);
    }

    // sigmoid tables + scan
    k_tab<<<NB*NT, 256>>>(dec, mesh);
    {
        dim3 g(NG, NB);
        k_scan<<<g, 256>>>(mesh, out);
    }

    // final + broadcasts
    k_final<<<(NB*NT + 255)/256, 256>>>(dec, hsr, msr, mor, out);
    k_bcast<<<(NB*MPTS*3 + 255)/256, 256>>>(mesh, out);
}

// round 14
// speedup vs baseline: 1.0475x; 1.0475x over previous
#include <cuda_runtime.h>
#include <math.h>

// ---------------- problem constants ----------------
#define MPTS 5151          // triangle mesh points (101*102/2)
#define NB   16            // batch
#define NT   1024          // decoder timesteps
#define NS   256           // encoder seq len
#define NH   256           // hidden
#define NG   21            // scan chunks per batch (21*16 = 336 CTAs ~ 2.3/SM)
#define TP   36            // mesh points per MLP CTA (144 CTAs = one balanced wave)
#define ACTW 260           // padded activation row stride (16B-aligned rows)

// output layout: b_out | density | m | initial_states | mesh
#define OFF_BOUT 0
#define OFF_DENS (NB*NT)                       // 16384
#define OFF_M    (OFF_DENS + NB*MPTS)          // 98800
#define OFF_INIT (OFF_M + NB*NT)               // 115184
#define OFF_MESH (OFF_INIT + NB*MPTS)          // 197600

// ---------------- device scratch (static, no allocs) ----------------
__device__ float g_density[MPTS];
__device__ float g_dpart[144];
__device__ float g_dsum;
__device__ float g_ctx[NB*NH];
__device__ float g_ctxp[NB*NH];
__device__ float g_wtab[NB*NT*256];            // per (b,t): [0..100]=w_up(alpha), [128..228]=w_dn(beta)
__device__ float g_mpart[NB*NG*NT];

__device__ __forceinline__ float sigmoid_acc(float x){
    return 1.0f / (1.0f + expf(-x));
}

// ---- f32x2 packed helpers (Blackwell FFMA2: only reachable via PTX) ----
__device__ __forceinline__ unsigned long long pk2(float x){
    unsigned long long r;
    unsigned u = __float_as_uint(x);
    asm("mov.b64 %0, {%1, %1};" : "=l"(r) : "r"(u));
    return r;
}
__device__ __forceinline__ void ffma2(unsigned long long &acc,
                                      unsigned long long a, unsigned long long b){
    asm("fma.rn.f32x2 %0, %1, %2, %0;" : "+l"(acc) : "l"(a), "l"(b));
}
__device__ __forceinline__ float2 up2(unsigned long long v){
    unsigned lo, hi;
    asm("mov.b64 {%0, %1}, %2;" : "=r"(lo), "=r"(hi) : "l"(v));
    float2 r; r.x = __uint_as_float(lo); r.y = __uint_as_float(hi);
    return r;
}

// ================= fused density MLP =================
// One CTA = 36 mesh points carried through input layer + 3 residual layers +
// output head, activations resident in shared memory. 192 threads:
// warp w owns points p0=6w..6w+5; lane owns 8 output columns j0=8*lane.
// Inner product uses f32x2 FMA: W pairs read directly as 64-bit from smem.
extern __shared__ float smdyn[];

__global__ void __launch_bounds__(192) k_mlp(const float* __restrict__ mesh,
    const float* __restrict__ Win, const float* __restrict__ bin,
    const float* __restrict__ Wr,  const float* __restrict__ br,
    const float* __restrict__ Wout, const float* __restrict__ bout)
{
    float* act = smdyn;                 // TP*ACTW floats
    float* ws  = smdyn + TP*ACTW;       // 32*NH floats (k-chunk of W)
    float* dsh = ws + 32*NH;            // TP floats (per-point density)
    int tid  = threadIdx.x;
    int lane = tid & 31, wid = tid >> 5;
    int p0 = wid * 6;
    int j0 = lane * 8;
    int pg = blockIdx.x * TP;

    // ---- input layer: act = relu(mesh @ Win + bin) ----
    {
        float be[6], al[6];
        #pragma unroll
        for (int i = 0; i < 6; i++){
            int p = pg + p0 + i;
            be[i] = 0.f; al[i] = 0.f;
            if (p < MPTS){ be[i] = mesh[2*p]; al[i] = mesh[2*p+1]; }
        }
        #pragma unroll
        for (int jj = 0; jj < 8; jj++){
            int j = j0 + jj;
            float w0 = Win[j], w1 = Win[NH+j], bb = bin[j];
            #pragma unroll
            for (int i = 0; i < 6; i++){
                float v = fmaf(be[i], w0, fmaf(al[i], w1, bb));
                act[(p0+i)*ACTW + j] = fmaxf(v, 0.f);
            }
        }
    }
    __syncthreads();

    // ---- 3 residual layers: act = act + relu(act @ W + b) ----
    for (int L = 0; L < 3; L++){
        const float* W    = Wr + L*NH*NH;
        const float* bias = br + L*NH;
        unsigned long long acc[6][4];
        #pragma unroll
        for (int i = 0; i < 6; i++)
            #pragma unroll
            for (int q = 0; q < 4; q++) acc[i][q] = 0ULL;

        for (int kc = 0; kc < NH; kc += 32){
            // stage 32xNH weight chunk (2048 float4, 192 threads)
            for (int idx = tid; idx < 2048; idx += 192){
                int row = idx >> 6, col = (idx & 63) * 4;
                *reinterpret_cast<float4*>(&ws[row*NH + col]) =
                    *reinterpret_cast<const float4*>(&W[(kc+row)*NH + col]);
            }
            __syncthreads();
            #pragma unroll 4
            for (int k = 0; k < 32; k++){
                unsigned long long ad[6];
                #pragma unroll
                for (int i = 0; i < 6; i++)
                    ad[i] = pk2(act[(p0+i)*ACTW + kc + k]);
                ulonglong2 w0 = *reinterpret_cast<const ulonglong2*>(&ws[k*NH + j0]);
                ulonglong2 w1 = *reinterpret_cast<const ulonglong2*>(&ws[k*NH + j0 + 4]);
                #pragma unroll
                for (int i = 0; i < 6; i++){
                    ffma2(acc[i][0], ad[i], w0.x);
                    ffma2(acc[i][1], ad[i], w0.y);
                    ffma2(acc[i][2], ad[i], w1.x);
                    ffma2(acc[i][3], ad[i], w1.y);
                }
            }
            __syncthreads();
        }
        // epilogue: own (p,j) cells only -> safe in-place after last sync
        float4 b0 = *reinterpret_cast<const float4*>(&bias[j0]);
        float4 b1 = *reinterpret_cast<const float4*>(&bias[j0+4]);
        #pragma unroll
        for (int i = 0; i < 6; i++){
            float* arow = &act[(p0+i)*ACTW + j0];
            float4 x0 = *reinterpret_cast<float4*>(arow);
            float4 x1 = *reinterpret_cast<float4*>(arow + 4);
            float2 f0 = up2(acc[i][0]), f1 = up2(acc[i][1]);
            float2 f2 = up2(acc[i][2]), f3 = up2(acc[i][3]);
            x0.x += fmaxf(f0.x + b0.x, 0.f);
            x0.y += fmaxf(f0.y + b0.y, 0.f);
            x0.z += fmaxf(f1.x + b0.z, 0.f);
            x0.w += fmaxf(f1.y + b0.w, 0.f);
            x1.x += fmaxf(f2.x + b1.x, 0.f);
            x1.y += fmaxf(f2.y + b1.y, 0.f);
            x1.z += fmaxf(f3.x + b1.z, 0.f);
            x1.w += fmaxf(f3.y + b1.w, 0.f);
            *reinterpret_cast<float4*>(arow)     = x0;
            *reinterpret_cast<float4*>(arow + 4) = x1;
        }
        __syncthreads();
    }

    // ---- output head: density = sigmoid(act @ Wout + bout) ----
    {
        float bo = bout[0];
        #pragma unroll
        for (int i = 0; i < 6; i++){
            int pl = p0 + i;
            float a = 0.f;
            #pragma unroll
            for (int q = 0; q < 8; q++){
                int h = lane + q*32;
                a = fmaf(act[pl*ACTW + h], Wout[h], a);
            }
            #pragma unroll
            for (int off = 16; off; off >>= 1)
                a += __shfl_xor_sync(0xffffffffu, a, off);
            if (lane == 0){
                int p = pg + pl;
                float dd = (p < MPTS) ? sigmoid_acc(a + bo) : 0.f;
                if (p < MPTS) g_density[p] = dd;
                dsh[pl] = dd;
            }
        }
    }
    __syncthreads();
    if (tid == 0){
        float s = 0.f;
        #pragma unroll
        for (int i = 0; i < TP; i++) s += dsh[i];
        g_dpart[blockIdx.x] = s;
    }
}

// ---------------- dsum over 144 CTA partials ----------------
__global__ void k_dsum(){
    __shared__ float sh[256];
    float a = (threadIdx.x < 144) ? g_dpart[threadIdx.x] : 0.f;
    sh[threadIdx.x] = a; __syncthreads();
    for (int s = 128; s; s >>= 1){
        if (threadIdx.x < (unsigned)s) sh[threadIdx.x] += sh[threadIdx.x+s];
        __syncthreads();
    }
    if (threadIdx.x == 0) g_dsum = sh[0];
}

// ---------------- encoder context ----------------
__global__ void k_ctx(const float* __restrict__ enc, const float* __restrict__ mask,
                      const float* __restrict__ Ws, const float* __restrict__ bs){
    __shared__ float e0[NS], e1[NS], mk[NS];
    int b = blockIdx.x, h = threadIdx.x;
    e0[h] = enc[(b*NS + h)*2];
    e1[h] = enc[(b*NS + h)*2 + 1];
    mk[h] = mask[b*NS + h];
    __syncthreads();
    float w0 = Ws[h], w1 = Ws[NH + h], bb = bs[h];
    float acc = 0.0f, ms = 0.0f;
    for (int s = 0; s < NS; s++){
        float v = fmaxf(fmaf(e0[s], w0, fmaf(e1[s], w1, bb)), 0.0f);
        acc = fmaf(v, mk[s], acc);
        ms += mk[s];
    }
    g_ctx[b*NH + h] = acc / fmaxf(ms, 1.0f);
}

__global__ void k_ctxp(const float* __restrict__ Wc){
    __shared__ float c[NH];
    int b = blockIdx.x, j = threadIdx.x;
    c[j] = g_ctx[b*NH + j];
    __syncthreads();
    float acc = 0.0f;
    #pragma unroll 4
    for (int h = 0; h < NH; h++) acc = fmaf(c[h], Wc[h*NH + j], acc);
    g_ctxp[b*NH + j] = acc;
}

// ---------------- initial states ----------------
__global__ void k_init(const float* __restrict__ mesh,
                       const float* __restrict__ Wm, const float* __restrict__ bm,
                       const float* __restrict__ Wo, const float* __restrict__ bo,
                       float* __restrict__ out){
    __shared__ float wm0[NH], wm1[NH], wm2[NH], wo[NH], pre[NH];
    int b = blockIdx.y;
    int tid = threadIdx.x;
    wm0[tid] = Wm[tid]; wm1[tid] = Wm[NH+tid]; wm2[tid] = Wm[2*NH+tid];
    wo[tid]  = Wo[tid];
    pre[tid] = g_ctxp[b*NH + tid] + bm[tid];
    __syncthreads();
    int p = blockIdx.x*256 + tid;
    if (p >= MPTS) return;
    float be = mesh[2*p], al = mesh[2*p+1], d = g_density[p];
    float acc = 0.0f;
    #pragma unroll 4
    for (int h = 0; h < NH; h++){
        float z = fmaf(be, wm0[h], fmaf(al, wm1[h], fmaf(d, wm2[h], pre[h])));
        z = fmaxf(z, 0.0f);
        acc = fmaf(z, wo[h], acc);
    }
    out[OFF_INIT + b*MPTS + p] = tanhf(acc + bo[0]);
}

// ---------------- sigmoid tables: per (b,t), 101 alpha + 101 beta values ----------------
__global__ void k_tab(const float* __restrict__ dec, const float* __restrict__ mesh){
    int q = blockIdx.x;              // q = b*NT + t
    int j = threadIdx.x;
    float h = dec[q];
    float v = 0.0f;
    if (j < 101){
        float gv = mesh[2*j + 1];    // grid values = alpha of first 101 points (beta=0 row)
        v = sigmoid_acc((h - gv) / 0.001f);
    } else if (j >= 128 && j < 229){
        float gv = mesh[2*(j-128) + 1];
        v = sigmoid_acc((gv - h) / 0.001f);
    }
    g_wtab[(size_t)q*256 + j] = v;
}

// ---------------- relay scan ----------------
// 1 point/thread, 256 pts/CTA, NG=21 chunks x 16 batches = 336 CTAs.
// Deferred reduction: threads write per-step partials to psum; after each
// 8-step block, warp w reduces step w (8 LDS + 5 shfl instead of 5 shfl/step).
// Next table block is prefetched during the reduce phase.
__global__ void __launch_bounds__(256) k_scan(const float* __restrict__ mesh,
                                              const float* __restrict__ outro){
    __shared__ float tabS[8][256];
    __shared__ float psum[8][256];
    int g = blockIdx.x, b = blockIdx.y;
    int tid = threadIdx.x, warp = tid >> 5, lane = tid & 31;
    int p = g*256 + tid;

    float s = 0.f, dn = 0.f; int ia = 0, ib = 128;
    if (p < MPTS){
        float be = mesh[2*p], al = mesh[2*p+1];
        ia = __float2int_rn(al * 100.0f);
        ib = __float2int_rn(be * 100.0f) + 128;
        dn = g_density[p];
        s  = outro[OFF_INIT + b*MPTS + p];
    }

    const float4* tg = reinterpret_cast<const float4*>(g_wtab + (size_t)b*NT*256);
    float4* ts4 = reinterpret_cast<float4*>(&tabS[0][0]);
    ts4[tid] = tg[tid]; ts4[tid + 256] = tg[tid + 256];   // preload bt=0

    for (int bt = 0; bt < NT/8; bt++){
        __syncthreads();                    // tab(bt) visible, psum(bt-1) consumed
        #pragma unroll
        for (int st = 0; st < 8; st++){
            float wu = tabS[st][ia];
            float wd = tabS[st][ib];
            s = fmaf(wu,  1.0f - s, s);     // s += wu*(1-s)
            s = fmaf(wd, -1.0f - s, s);     // s += wd*(-1-s)
            psum[st][tid] = dn * s;
        }
        __syncthreads();                    // psum ready, tabS free
        if (bt + 1 < NT/8){                 // prefetch next table block
            int o = (bt + 1) * 512;
            ts4[tid] = tg[o + tid]; ts4[tid + 256] = tg[o + tid + 256];
        }
        float a = 0.f;                      // warp w reduces step w
        #pragma unroll
        for (int q = 0; q < 8; q++) a += psum[warp][lane + q*32];
        #pragma unroll
        for (int off = 16; off; off >>= 1)
            a += __shfl_xor_sync(0xffffffffu, a, off);
        if (lane == 0) g_mpart[((b*NG) + g)*NT + bt*8 + warp] = a;
    }
}

// ---------------- final: m, b_out ----------------
__global__ void k_final(const float* __restrict__ dec,
                        const float* __restrict__ hsr, const float* __restrict__ msr,
                        const float* __restrict__ mor, float* __restrict__ out){
    int idx = blockIdx.x*256 + threadIdx.x;
    if (idx >= NB*NT) return;
    int b = idx >> 10, t = idx & 1023;
    float a = 0.0f;
    #pragma unroll
    for (int g = 0; g < NG; g++) a += g_mpart[((b*NG)+g)*NT + t];
    float m = a / g_dsum;
    float hs = 10.0f * sigmoid_acc(hsr[0]);
    float ms = 10.0f * sigmoid_acc(msr[0]);
    float mo = fmaf(20.0f, sigmoid_acc(mor[0]), -10.0f);
    float h = dec[idx];
    out[OFF_M + idx] = m;
    out[OFF_BOUT + idx] = fmaf(hs, h, fmaf(ms, m, mo));
}

// ---------------- broadcasts: density, mesh ----------------
__global__ void k_bcast(const float* __restrict__ mesh, float* __restrict__ out){
    int idx = blockIdx.x*256 + threadIdx.x;
    const int nd = NB*MPTS;
    if (idx < nd){
        out[OFF_DENS + idx] = g_density[idx % MPTS];
    } else {
        int i2 = idx - nd;
        if (i2 < NB*MPTS*2)
            out[OFF_MESH + i2] = mesh[i2 % (MPTS*2)];
    }
}

// ---------------- launch ----------------
extern "C" void kernel_launch(void* const* d_in, const int* in_sizes, int n_in,
                              void* d_out, int out_size){
    const float* enc   = (const float*)d_in[0];
    const float* dec   = (const float*)d_in[1];
    const float* emask = (const float*)d_in[2];
    const float* mesh  = (const float*)d_in[3];
    const float* Win   = (const float*)d_in[4];
    const float* bin   = (const float*)d_in[5];
    const float* Wr    = (const float*)d_in[6];
    const float* br    = (const float*)d_in[7];
    const float* Wout  = (const float*)d_in[8];
    const float* bout  = (const float*)d_in[9];
    const float* Ws    = (const float*)d_in[10];
    const float* bs    = (const float*)d_in[11];
    const float* Wm    = (const float*)d_in[12];
    const float* Wc    = (const float*)d_in[13];
    const float* bm    = (const float*)d_in[14];
    const float* Wo    = (const float*)d_in[15];
    const float* bo    = (const float*)d_in[16];
    const float* hsr   = (const float*)d_in[17];
    const float* msr   = (const float*)d_in[18];
    const float* mor   = (const float*)d_in[19];
    float* out = (float*)d_out;

    // fused density MLP (batch-independent): 144 CTAs, one wave
    const int smbytes = (TP*ACTW + 32*NH + 64) * (int)sizeof(float);  // ~70.5KB
    static int attr_done = 0;
    if (!attr_done){
        cudaFuncSetAttribute(k_mlp, cudaFuncAttributeMaxDynamicSharedMemorySize, smbytes);
        attr_done = 1;
    }
    k_mlp<<<(MPTS + TP - 1)/TP, 192, smbytes>>>(mesh, Win, bin, Wr, br, Wout, bout);
    k_dsum<<<1, 256>>>();

    // encoder path
    k_ctx<<<NB, 256>>>(enc, emask, Ws, bs);
    k_ctxp<<<NB, 256>>>(Wc);

    // initial states (writes d_out init region)
    {
        dim3 g((MPTS + 255)/256, NB);
        k_init<<<g, 256>>>(mesh, Wm, bm, Wo, bo, out);
    }

    // sigmoid tables + scan
    k_tab<<<NB*NT, 256>>>(dec, mesh);
    {
        dim3 g(NG, NB);
        k_scan<<<g, 256>>>(mesh, out);
    }

    // final + broadcasts
    k_final<<<(NB*NT + 255)/256, 256>>>(dec, hsr, msr, mor, out);
    k_bcast<<<(NB*MPTS*3 + 255)/256, 256>>>(mesh, out);
}

// round 15
// speedup vs baseline: 1.0504x; 1.0028x over previous
#include <cuda_runtime.h>
#include <math.h>

// ---------------- problem constants ----------------
#define MPTS 5151          // triangle mesh points (101*102/2)
#define NB   16            // batch
#define NT   1024          // decoder timesteps
#define NS   256           // encoder seq len
#define NH   256           // hidden
#define NG   21            // scan chunks per batch (21*16 = 336 CTAs ~ 2.3/SM)
#define TP   36            // mesh points per MLP CTA (144 CTAs = one balanced wave)
#define ACTW 260           // padded activation row stride (16B-aligned rows)

// output layout: b_out | density | m | initial_states | mesh
#define OFF_BOUT 0
#define OFF_DENS (NB*NT)                       // 16384
#define OFF_M    (OFF_DENS + NB*MPTS)          // 98800
#define OFF_INIT (OFF_M + NB*NT)               // 115184
#define OFF_MESH (OFF_INIT + NB*MPTS)          // 197600

// ---------------- device scratch (static, no allocs) ----------------
__device__ float g_density[MPTS];
__device__ float g_dpart[144];
__device__ float g_dsum;
__device__ float g_ctx[NB*NH];
__device__ float g_ctxp[NB*NH];
__device__ float g_wtab[NB*NT*256];            // per (b,t): [0..100]=w_up(alpha), [128..228]=w_dn(beta)
__device__ float g_mpart[NB*NG*NT];

__device__ __forceinline__ float sigmoid_acc(float x){
    return 1.0f / (1.0f + expf(-x));
}

// ---- f32x2 packed helpers (Blackwell FFMA2: only reachable via PTX) ----
__device__ __forceinline__ unsigned long long pk2(float x){
    unsigned long long r;
    unsigned u = __float_as_uint(x);
    asm("mov.b64 %0, {%1, %1};" : "=l"(r) : "r"(u));
    return r;
}
__device__ __forceinline__ void ffma2(unsigned long long &acc,
                                      unsigned long long a, unsigned long long b){
    asm("fma.rn.f32x2 %0, %1, %2, %0;" : "+l"(acc) : "l"(a), "l"(b));
}
__device__ __forceinline__ float2 up2(unsigned long long v){
    unsigned lo, hi;
    asm("mov.b64 {%0, %1}, %2;" : "=r"(lo), "=r"(hi) : "l"(v));
    float2 r; r.x = __uint_as_float(lo); r.y = __uint_as_float(hi);
    return r;
}

// ================= fused density MLP =================
// One CTA = 36 mesh points carried through input layer + 3 residual layers +
// output head, activations resident in shared memory. 192 threads:
// warp w owns points p0=6w..6w+5; lane owns 8 output columns j0=8*lane.
// Inner product uses f32x2 FMA: W pairs read directly as 64-bit from smem.
extern __shared__ float smdyn[];

__global__ void __launch_bounds__(192) k_mlp(const float* __restrict__ mesh,
    const float* __restrict__ Win, const float* __restrict__ bin,
    const float* __restrict__ Wr,  const float* __restrict__ br,
    const float* __restrict__ Wout, const float* __restrict__ bout)
{
    float* act = smdyn;                 // TP*ACTW floats
    float* ws  = smdyn + TP*ACTW;       // 32*NH floats (k-chunk of W)
    float* dsh = ws + 32*NH;            // TP floats (per-point density)
    int tid  = threadIdx.x;
    int lane = tid & 31, wid = tid >> 5;
    int p0 = wid * 6;
    int j0 = lane * 8;
    int pg = blockIdx.x * TP;

    // ---- input layer: act = relu(mesh @ Win + bin) ----
    {
        float be[6], al[6];
        #pragma unroll
        for (int i = 0; i < 6; i++){
            int p = pg + p0 + i;
            be[i] = 0.f; al[i] = 0.f;
            if (p < MPTS){ be[i] = mesh[2*p]; al[i] = mesh[2*p+1]; }
        }
        #pragma unroll
        for (int jj = 0; jj < 8; jj++){
            int j = j0 + jj;
            float w0 = Win[j], w1 = Win[NH+j], bb = bin[j];
            #pragma unroll
            for (int i = 0; i < 6; i++){
                float v = fmaf(be[i], w0, fmaf(al[i], w1, bb));
                act[(p0+i)*ACTW + j] = fmaxf(v, 0.f);
            }
        }
    }
    __syncthreads();

    // ---- 3 residual layers: act = act + relu(act @ W + b) ----
    for (int L = 0; L < 3; L++){
        const float* W    = Wr + L*NH*NH;
        const float* bias = br + L*NH;
        unsigned long long acc[6][4];
        #pragma unroll
        for (int i = 0; i < 6; i++)
            #pragma unroll
            for (int q = 0; q < 4; q++) acc[i][q] = 0ULL;

        for (int kc = 0; kc < NH; kc += 32){
            // stage 32xNH weight chunk (2048 float4, 192 threads)
            for (int idx = tid; idx < 2048; idx += 192){
                int row = idx >> 6, col = (idx & 63) * 4;
                *reinterpret_cast<float4*>(&ws[row*NH + col]) =
                    *reinterpret_cast<const float4*>(&W[(kc+row)*NH + col]);
            }
            __syncthreads();
            #pragma unroll 4
            for (int k = 0; k < 32; k++){
                unsigned long long ad[6];
                #pragma unroll
                for (int i = 0; i < 6; i++)
                    ad[i] = pk2(act[(p0+i)*ACTW + kc + k]);
                ulonglong2 w0 = *reinterpret_cast<const ulonglong2*>(&ws[k*NH + j0]);
                ulonglong2 w1 = *reinterpret_cast<const ulonglong2*>(&ws[k*NH + j0 + 4]);
                #pragma unroll
                for (int i = 0; i < 6; i++){
                    ffma2(acc[i][0], ad[i], w0.x);
                    ffma2(acc[i][1], ad[i], w0.y);
                    ffma2(acc[i][2], ad[i], w1.x);
                    ffma2(acc[i][3], ad[i], w1.y);
                }
            }
            __syncthreads();
        }
        // epilogue: own (p,j) cells only -> safe in-place after last sync
        float4 b0 = *reinterpret_cast<const float4*>(&bias[j0]);
        float4 b1 = *reinterpret_cast<const float4*>(&bias[j0+4]);
        #pragma unroll
        for (int i = 0; i < 6; i++){
            float* arow = &act[(p0+i)*ACTW + j0];
            float4 x0 = *reinterpret_cast<float4*>(arow);
            float4 x1 = *reinterpret_cast<float4*>(arow + 4);
            float2 f0 = up2(acc[i][0]), f1 = up2(acc[i][1]);
            float2 f2 = up2(acc[i][2]), f3 = up2(acc[i][3]);
            x0.x += fmaxf(f0.x + b0.x, 0.f);
            x0.y += fmaxf(f0.y + b0.y, 0.f);
            x0.z += fmaxf(f1.x + b0.z, 0.f);
            x0.w += fmaxf(f1.y + b0.w, 0.f);
            x1.x += fmaxf(f2.x + b1.x, 0.f);
            x1.y += fmaxf(f2.y + b1.y, 0.f);
            x1.z += fmaxf(f3.x + b1.z, 0.f);
            x1.w += fmaxf(f3.y + b1.w, 0.f);
            *reinterpret_cast<float4*>(arow)     = x0;
            *reinterpret_cast<float4*>(arow + 4) = x1;
        }
        __syncthreads();
    }

    // ---- output head: density = sigmoid(act @ Wout + bout) ----
    {
        float bo = bout[0];
        #pragma unroll
        for (int i = 0; i < 6; i++){
            int pl = p0 + i;
            float a = 0.f;
            #pragma unroll
            for (int q = 0; q < 8; q++){
                int h = lane + q*32;
                a = fmaf(act[pl*ACTW + h], Wout[h], a);
            }
            #pragma unroll
            for (int off = 16; off; off >>= 1)
                a += __shfl_xor_sync(0xffffffffu, a, off);
            if (lane == 0){
                int p = pg + pl;
                float dd = (p < MPTS) ? sigmoid_acc(a + bo) : 0.f;
                if (p < MPTS) g_density[p] = dd;
                dsh[pl] = dd;
            }
        }
    }
    __syncthreads();
    if (tid == 0){
        float s = 0.f;
        #pragma unroll
        for (int i = 0; i < TP; i++) s += dsh[i];
        g_dpart[blockIdx.x] = s;
    }
}

// ---------------- dsum over 144 CTA partials ----------------
__global__ void k_dsum(){
    __shared__ float sh[256];
    float a = (threadIdx.x < 144) ? g_dpart[threadIdx.x] : 0.f;
    sh[threadIdx.x] = a; __syncthreads();
    for (int s = 128; s; s >>= 1){
        if (threadIdx.x < (unsigned)s) sh[threadIdx.x] += sh[threadIdx.x+s];
        __syncthreads();
    }
    if (threadIdx.x == 0) g_dsum = sh[0];
}

// ---------------- encoder context ----------------
__global__ void k_ctx(const float* __restrict__ enc, const float* __restrict__ mask,
                      const float* __restrict__ Ws, const float* __restrict__ bs){
    __shared__ float e0[NS], e1[NS], mk[NS];
    int b = blockIdx.x, h = threadIdx.x;
    e0[h] = enc[(b*NS + h)*2];
    e1[h] = enc[(b*NS + h)*2 + 1];
    mk[h] = mask[b*NS + h];
    __syncthreads();
    float w0 = Ws[h], w1 = Ws[NH + h], bb = bs[h];
    float acc = 0.0f, ms = 0.0f;
    for (int s = 0; s < NS; s++){
        float v = fmaxf(fmaf(e0[s], w0, fmaf(e1[s], w1, bb)), 0.0f);
        acc = fmaf(v, mk[s], acc);
        ms += mk[s];
    }
    g_ctx[b*NH + h] = acc / fmaxf(ms, 1.0f);
}

__global__ void k_ctxp(const float* __restrict__ Wc){
    __shared__ float c[NH];
    int b = blockIdx.x, j = threadIdx.x;
    c[j] = g_ctx[b*NH + j];
    __syncthreads();
    float acc = 0.0f;
    #pragma unroll 4
    for (int h = 0; h < NH; h++) acc = fmaf(c[h], Wc[h*NH + j], acc);
    g_ctxp[b*NH + j] = acc;
}

// ---------------- initial states ----------------
__global__ void k_init(const float* __restrict__ mesh,
                       const float* __restrict__ Wm, const float* __restrict__ bm,
                       const float* __restrict__ Wo, const float* __restrict__ bo,
                       float* __restrict__ out){
    __shared__ float wm0[NH], wm1[NH], wm2[NH], wo[NH], pre[NH];
    int b = blockIdx.y;
    int tid = threadIdx.x;
    wm0[tid] = Wm[tid]; wm1[tid] = Wm[NH+tid]; wm2[tid] = Wm[2*NH+tid];
    wo[tid]  = Wo[tid];
    pre[tid] = g_ctxp[b*NH + tid] + bm[tid];
    __syncthreads();
    int p = blockIdx.x*256 + tid;
    if (p >= MPTS) return;
    float be = mesh[2*p], al = mesh[2*p+1], d = g_density[p];
    float acc = 0.0f;
    #pragma unroll 4
    for (int h = 0; h < NH; h++){
        float z = fmaf(be, wm0[h], fmaf(al, wm1[h], fmaf(d, wm2[h], pre[h])));
        z = fmaxf(z, 0.0f);
        acc = fmaf(z, wo[h], acc);
    }
    out[OFF_INIT + b*MPTS + p] = tanhf(acc + bo[0]);
}

// ---------------- sigmoid tables: per (b,t), 101 alpha + 101 beta values ----------------
__global__ void k_tab(const float* __restrict__ dec, const float* __restrict__ mesh){
    int q = blockIdx.x;              // q = b*NT + t
    int j = threadIdx.x;
    float h = dec[q];
    float v = 0.0f;
    if (j < 101){
        float gv = mesh[2*j + 1];    // grid values = alpha of first 101 points (beta=0 row)
        v = sigmoid_acc((h - gv) / 0.001f);
    } else if (j >= 128 && j < 229){
        float gv = mesh[2*(j-128) + 1];
        v = sigmoid_acc((gv - h) / 0.001f);
    }
    g_wtab[(size_t)q*256 + j] = v;
}

// ---------------- relay scan ----------------
// 1 point/thread, 256 pts/CTA, NG=21 chunks x 16 batches = 336 CTAs.
// Deferred reduction: threads write per-step partials to psum; after each
// 8-step block, warp w reduces step w (8 LDS + 5 shfl instead of 5 shfl/step).
// Next table block is prefetched during the reduce phase.
__global__ void __launch_bounds__(256) k_scan(const float* __restrict__ mesh,
                                              const float* __restrict__ outro){
    __shared__ float tabS[8][256];
    __shared__ float psum[8][256];
    int g = blockIdx.x, b = blockIdx.y;
    int tid = threadIdx.x, warp = tid >> 5, lane = tid & 31;
    int p = g*256 + tid;

    float s = 0.f, dn = 0.f; int ia = 0, ib = 128;
    if (p < MPTS){
        float be = mesh[2*p], al = mesh[2*p+1];
        ia = __float2int_rn(al * 100.0f);
        ib = __float2int_rn(be * 100.0f) + 128;
        dn = g_density[p];
        s  = outro[OFF_INIT + b*MPTS + p];
    }

    const float4* tg = reinterpret_cast<const float4*>(g_wtab + (size_t)b*NT*256);
    float4* ts4 = reinterpret_cast<float4*>(&tabS[0][0]);
    ts4[tid] = tg[tid]; ts4[tid + 256] = tg[tid + 256];   // preload bt=0

    for (int bt = 0; bt < NT/8; bt++){
        __syncthreads();                    // tab(bt) visible, psum(bt-1) consumed
        #pragma unroll
        for (int st = 0; st < 8; st++){
            float wu = tabS[st][ia];
            float wd = tabS[st][ib];
            s = fmaf(wu,  1.0f - s, s);     // s += wu*(1-s)
            s = fmaf(wd, -1.0f - s, s);     // s += wd*(-1-s)
            psum[st][tid] = dn * s;
        }
        __syncthreads();                    // psum ready, tabS free
        if (bt + 1 < NT/8){                 // prefetch next table block
            int o = (bt + 1) * 512;
            ts4[tid] = tg[o + tid]; ts4[tid + 256] = tg[o + tid + 256];
        }
        float a = 0.f;                      // warp w reduces step w
        #pragma unroll
        for (int q = 0; q < 8; q++) a += psum[warp][lane + q*32];
        #pragma unroll
        for (int off = 16; off; off >>= 1)
            a += __shfl_xor_sync(0xffffffffu, a, off);
        if (lane == 0) g_mpart[((b*NG) + g)*NT + bt*8 + warp] = a;
    }
}

// ---------------- final: m, b_out ----------------
__global__ void k_final(const float* __restrict__ dec,
                        const float* __restrict__ hsr, const float* __restrict__ msr,
                        const float* __restrict__ mor, float* __restrict__ out){
    int idx = blockIdx.x*256 + threadIdx.x;
    if (idx >= NB*NT) return;
    int b = idx >> 10, t = idx & 1023;
    float a = 0.0f;
    #pragma unroll
    for (int g = 0; g < NG; g++) a += g_mpart[((b*NG)+g)*NT + t];
    float m = a / g_dsum;
    float hs = 10.0f * sigmoid_acc(hsr[0]);
    float ms = 10.0f * sigmoid_acc(msr[0]);
    float mo = fmaf(20.0f, sigmoid_acc(mor[0]), -10.0f);
    float h = dec[idx];
    out[OFF_M + idx] = m;
    out[OFF_BOUT + idx] = fmaf(hs, h, fmaf(ms, m, mo));
}

// ---------------- broadcasts: density, mesh ----------------
__global__ void k_bcast(const float* __restrict__ mesh, float* __restrict__ out){
    int idx = blockIdx.x*256 + threadIdx.x;
    const int nd = NB*MPTS;
    if (idx < nd){
        out[OFF_DENS + idx] = g_density[idx % MPTS];
    } else {
        int i2 = idx - nd;
        if (i2 < NB*MPTS*2)
            out[OFF_MESH + i2] = mesh[i2 % (MPTS*2)];
    }
}

// ---------------- launch ----------------
extern "C" void kernel_launch(void* const* d_in, const int* in_sizes, int n_in,
                              void* d_out, int out_size){
    const float* enc   = (const float*)d_in[0];
    const float* dec   = (const float*)d_in[1];
    const float* emask = (const float*)d_in[2];
    const float* mesh  = (const float*)d_in[3];
    const float* Win   = (const float*)d_in[4];
    const float* bin   = (const float*)d_in[5];
    const float* Wr    = (const float*)d_in[6];
    const float* br    = (const float*)d_in[7];
    const float* Wout  = (const float*)d_in[8];
    const float* bout  = (const float*)d_in[9];
    const float* Ws    = (const float*)d_in[10];
    const float* bs    = (const float*)d_in[11];
    const float* Wm    = (const float*)d_in[12];
    const float* Wc    = (const float*)d_in[13];
    const float* bm    = (const float*)d_in[14];
    const float* Wo    = (const float*)d_in[15];
    const float* bo    = (const float*)d_in[16];
    const float* hsr   = (const float*)d_in[17];
    const float* msr   = (const float*)d_in[18];
    const float* mor   = (const float*)d_in[19];
    float* out = (float*)d_out;

    // fused density MLP (batch-independent): 144 CTAs, one wave
    const int smbytes = (TP*ACTW + 32*NH + 64) * (int)sizeof(float);  // ~70.5KB
    static int attr_done = 0;
    if (!attr_done){
        cudaFuncSetAttribute(k_mlp, cudaFuncAttributeMaxDynamicSharedMemorySize, smbytes);
        attr_done = 1;
    }
    k_mlp<<<(MPTS + TP - 1)/TP, 192, smbytes>>>(mesh, Win, bin, Wr, br, Wout, bout);
    k_dsum<<<1, 256>>>();

    // encoder path
    k_ctx<<<NB, 256>>>(enc, emask, Ws, bs);
    k_ctxp<<<NB, 256>>>(Wc);

    // initial states (writes d_out init region)
    {
        dim3 g((MPTS + 255)/256, NB);
        k_init<<<g, 256>>>(mesh, Wm, bm, Wo, bo, out);
    }

    // sigmoid tables + scan
    k_tab<<<NB*NT, 256>>>(dec, mesh);
    {
        dim3 g(NG, NB);
        k_scan<<<g, 256>>>(mesh, out);
    }

    // final + broadcasts
    k_final<<<(NB*NT + 255)/256, 256>>>(dec, hsr, msr, mor, out);
    k_bcast<<<(NB*MPTS*3 + 255)/256, 256>>>(mesh, out);
}